// round 6
// baseline (speedup 1.0000x reference)
#include <cuda_runtime.h>
#include <math.h>

// ---------------- problem dims ----------------
// img (8,160,240,3) -> conv1 6x6x3x32 -> (8,155,235,32) -> pool -> (8,77,117,32)
// conv2 3x3x32x64 -> (8,75,115,64) -> pool -> (8,37,57,64)
// conv3 3x3x64x128 -> (8,35,55,128) -> flatten 246400
// dense1 246400x256 relu -> dense2 256x38400 -> transform -> pred (8,2400,16)
// NMS per (img, class in 0..2) over 4800 boxes -> keep (8,3,4800)

#define B_IMG 8
#define F_IN 246400
#define NCELL 2400
#define NBOXES 4800
#define PRED_ELEMS (B_IMG * NCELL * 16)       // 307200
#define KEEP_BASE PRED_ELEMS
#define NSPLIT 963
#define KC 256

// ---------------- scratch (device globals; no allocations) ----------------
__device__ float g_c1[9324800];   // (8,155,235,32)
__device__ float g_p1[2306304];   // (8,77,117,32)
__device__ float g_c2[4416000];   // (8,75,115,64)
__device__ float g_p2[1079808];   // (8,37,57,64)
__device__ float g_c3[1971200];   // (8,35,55,128) = dense1 input
__device__ float g_part[1972224]; // (963,8,256) dense1 split-K partials
__device__ float g_d1[2048];      // (8,256) dense1 output (post-relu)

__device__ __forceinline__ float sigf(float x) { return 1.f / (1.f + expf(-x)); }

// ---------------- generic direct conv + relu ----------------
// smem weights layout: [kk][ci4][cc][cg]  (cg contiguous -> conflict-free LDS.128)
// smem patch  layout: [py][px][ci4] of float4 (4 input channels)
template<int KH, int KW, int CI, int CIP4, int COB, int TX, int TY>
__global__ void conv_relu_k(const float* __restrict__ in, const float* __restrict__ w,
                            const float* __restrict__ bias, float* __restrict__ out,
                            int IH, int IW, int OH, int OW, int CO, int coH)
{
    constexpr int NCO4 = COB / 4;
    constexpr int PR = TY + KH - 1, PC = TX + KW - 1;
    constexpr int NW4 = KH * KW * CIP4 * COB;  // float4 elements
    constexpr int NP4 = PR * PC * CIP4;
    constexpr int NTHR = NCO4 * TX;

    extern __shared__ float4 sm4[];
    float4* ws = sm4;
    float4* ps = sm4 + NW4;

    const int tid = threadIdx.x;
    const int cg  = tid % NCO4;
    const int xo  = tid / NCO4;
    const int z   = blockIdx.z;
    const int img = z / coH;
    const int co0 = (z % coH) * COB;
    const int y0  = blockIdx.y * TY;
    const int x0  = blockIdx.x * TX;

    // load weights -> smem, swizzled layout
    for (int idx = tid; idx < NW4; idx += NTHR) {
        int cgi = idx % NCO4;
        int r   = idx / NCO4;
        int cc  = r % 4;  r /= 4;
        int ci4 = r % CIP4;
        int kk  = r / CIP4;
        int co  = cgi * 4 + cc;
        int cb  = ci4 * 4;
        const float* wp = w + (size_t)(kk * CI) * CO + (co0 + co);
        float4 v;
        v.x = (cb + 0 < CI) ? wp[(size_t)(cb + 0) * CO] : 0.f;
        v.y = (cb + 1 < CI) ? wp[(size_t)(cb + 1) * CO] : 0.f;
        v.z = (cb + 2 < CI) ? wp[(size_t)(cb + 2) * CO] : 0.f;
        v.w = (cb + 3 < CI) ? wp[(size_t)(cb + 3) * CO] : 0.f;
        ws[idx] = v;
    }
    // load input patch -> smem
    for (int idx = tid; idx < NP4; idx += NTHR) {
        int ci4 = idx % CIP4;
        int c2  = idx / CIP4;
        int px  = c2 % PC, py = c2 / PC;
        int iy  = y0 + py, ix = x0 + px;
        float4 v = make_float4(0.f, 0.f, 0.f, 0.f);
        if (iy < IH && ix < IW) {
            const float* p = in + ((size_t)(img * IH + iy) * IW + ix) * CI + ci4 * 4;
            if (CI & 3) { v.x = p[0]; v.y = p[1]; v.z = p[2]; }
            else        { v = *(const float4*)p; }
        }
        ps[idx] = v;
    }
    __syncthreads();

    float4 acc[TY];
#pragma unroll
    for (int yy = 0; yy < TY; yy++) acc[yy] = make_float4(0.f, 0.f, 0.f, 0.f);

#pragma unroll 1
    for (int kk = 0; kk < KH * KW; kk++) {
        const int ky = kk / KW, kx = kk % KW;
#pragma unroll 4
        for (int ci4 = 0; ci4 < CIP4; ci4++) {
            const float4* wb = ws + ((kk * CIP4 + ci4) * 4) * NCO4 + cg;
            float4 w0 = wb[0 * NCO4];
            float4 w1 = wb[1 * NCO4];
            float4 w2 = wb[2 * NCO4];
            float4 w3 = wb[3 * NCO4];
#pragma unroll
            for (int yy = 0; yy < TY; yy++) {
                float4 pv = ps[((yy + ky) * PC + xo + kx) * CIP4 + ci4];
                acc[yy].x += pv.x * w0.x + pv.y * w0.y + pv.z * w0.z + pv.w * w0.w;
                acc[yy].y += pv.x * w1.x + pv.y * w1.y + pv.z * w1.z + pv.w * w1.w;
                acc[yy].z += pv.x * w2.x + pv.y * w2.y + pv.z * w2.z + pv.w * w2.w;
                acc[yy].w += pv.x * w3.x + pv.y * w3.y + pv.z * w3.z + pv.w * w3.w;
            }
        }
    }

    const int x = x0 + xo;
    if (x < OW) {
        const int co = co0 + cg * 4;
        float4 bv = *(const float4*)(bias + co);
#pragma unroll
        for (int yy = 0; yy < TY; yy++) {
            int y = y0 + yy;
            if (y < OH) {
                float4 r;
                r.x = fmaxf(acc[yy].x + bv.x, 0.f);
                r.y = fmaxf(acc[yy].y + bv.y, 0.f);
                r.z = fmaxf(acc[yy].z + bv.z, 0.f);
                r.w = fmaxf(acc[yy].w + bv.w, 0.f);
                *(float4*)(out + ((size_t)(img * OH + y) * OW + x) * CO + co) = r;
            }
        }
    }
}

// ---------------- 2x2 max pool, stride 2, VALID ----------------
__global__ void pool_k(const float* __restrict__ in, float* __restrict__ out,
                       int IH, int IW, int OH, int OW, int C, int total)
{
    int idx = blockIdx.x * blockDim.x + threadIdx.x;
    if (idx >= total) return;
    int c = idx % C; int t = idx / C;
    int x = t % OW;  t /= OW;
    int y = t % OH;  int img = t / OH;
    const float* p = in + ((size_t)(img * IH + 2 * y) * IW + 2 * x) * C + c;
    float a = p[0], b = p[C];
    float cc = p[(size_t)IW * C], d = p[(size_t)IW * C + C];
    out[idx] = fmaxf(fmaxf(a, b), fmaxf(cc, d));
}

// ---------------- dense1 split-K ----------------
__global__ void d1_partial_k(const float* __restrict__ x, const float* __restrict__ wd1,
                             float* __restrict__ part)
{
    __shared__ float xs[B_IMG][KC];
    const int s = blockIdx.x;
    const int k0 = s * KC;
    const int tid = threadIdx.x; // 64
    for (int i = tid; i < B_IMG * KC; i += 64) {
        int b = i >> 8, kk = i & 255;
        int k = k0 + kk;
        xs[b][kk] = (k < F_IN) ? x[(size_t)b * F_IN + k] : 0.f;
    }
    __syncthreads();
    float4 acc[B_IMG];
#pragma unroll
    for (int b = 0; b < B_IMG; b++) acc[b] = make_float4(0.f, 0.f, 0.f, 0.f);
    const int kmax = min(KC, F_IN - k0);
    const float* wp = wd1 + (size_t)k0 * 256 + tid * 4;
#pragma unroll 4
    for (int kk = 0; kk < kmax; kk++) {
        float4 w = *(const float4*)wp; wp += 256;
#pragma unroll
        for (int b = 0; b < B_IMG; b++) {
            float xv = xs[b][kk];
            acc[b].x += xv * w.x; acc[b].y += xv * w.y;
            acc[b].z += xv * w.z; acc[b].w += xv * w.w;
        }
    }
#pragma unroll
    for (int b = 0; b < B_IMG; b++)
        *(float4*)(part + ((size_t)s * B_IMG + b) * 256 + tid * 4) = acc[b];
}

__global__ void d1_reduce_k(const float* __restrict__ part, const float* __restrict__ bd1,
                            float* __restrict__ d1o)
{
    int b = blockIdx.x, j = threadIdx.x;
    float s = 0.f;
    for (int si = 0; si < NSPLIT; si++)
        s += part[((size_t)si * B_IMG + b) * 256 + j];
    d1o[b * 256 + j] = fmaxf(s + bd1[j], 0.f);
}

// ---------------- dense2 + predict transform ----------------
__global__ void d2_transform_k(const float* __restrict__ d1, const float* __restrict__ wd2,
                               const float* __restrict__ bd2, float* __restrict__ pred)
{
    __shared__ float xs[B_IMG][256];
    const int tid = threadIdx.x; // 256
    for (int i = tid; i < B_IMG * 256; i += 256) xs[i >> 8][i & 255] = d1[i];
    __syncthreads();
    const int j = blockIdx.x * 256 + tid; // < 38400
    float acc[B_IMG];
#pragma unroll
    for (int b = 0; b < B_IMG; b++) acc[b] = 0.f;
    const float* wp = wd2 + j;
#pragma unroll 4
    for (int k = 0; k < 256; k++) {
        float wv = wp[(size_t)k * 38400];
#pragma unroll
        for (int b = 0; b < B_IMG; b++) acc[b] += xs[b][k] * wv;
    }
    const float bb = bd2[j];
    const int c = j & 15, cell = j >> 4;
    float off = 0.f;
    if (c == 0 || c == 8) off = (float)(cell % 60);
    else if (c == 1 || c == 9) off = (float)(cell / 60);
#pragma unroll
    for (int b = 0; b < B_IMG; b++) {
        float p = acc[b] + bb;
        float v;
        if (c < 2)        v = (sigf(p) + off) * 4.f;
        else if (c == 2)  v = expf(p) * 240.f;   // 60*4
        else if (c == 3)  v = expf(p) * 120.f;   // 30*4
        else if (c < 8)   v = sigf(p);
        else if (c < 10)  v = (p + off) * 4.f;
        else if (c == 10) v = expf(p) * 80.f;    // 20*4
        else if (c == 11) v = expf(p) * 160.f;   // 40*4
        else if (c == 12) v = p;
        else              v = sigf(p);
        pred[((size_t)b * NCELL + cell) * 16 + c] = v;
    }
}

// ---------------- per (img,class) greedy NMS ----------------
// smem: key[8192] f, val[8192] i, bx/by/bw/bh[4800] f, keepw[150] u32, cnt
#define NMS_SMEM (8192*4 + 8192*4 + 4800*4*4 + 150*4 + 4)
__global__ void nms_k(const float* __restrict__ pred, float* __restrict__ out)
{
    const int cls = blockIdx.x;
    const int img = blockIdx.y;
    extern __shared__ char smraw[];
    float*    key   = (float*)smraw;
    int*      val   = (int*)(key + 8192);
    float*    bx    = (float*)(val + 8192);
    float*    by    = bx + NBOXES;
    float*    bw    = by + NBOXES;
    float*    bh    = bw + NBOXES;
    unsigned* keepw = (unsigned*)(bh + NBOXES);
    int*      cntp  = (int*)(keepw + 150);
    const int tid = threadIdx.x; // 1024
    const float* pb = pred + (size_t)img * (NCELL * 16);

    if (tid == 0) *cntp = 0;
    for (int i = tid; i < 8192; i += 1024) {
        float sc = -2.f;
        if (i < NBOXES) {
            int base = (i < NCELL) ? i * 16 : (i - NCELL) * 16 + 8;
            float conf = pb[base + 4];
            float c5 = pb[base + 5], c6 = pb[base + 6], c7 = pb[base + 7];
            int ci = 0; float bst = c5;
            if (c6 > bst) { bst = c6; ci = 1; }
            if (c7 > bst) { ci = 2; }
            sc = (conf > 0.5f && ci == cls) ? conf : -1.f;
        }
        key[i] = sc; val[i] = i;
    }
    __syncthreads();

    // bitonic sort, descending by key
    for (int k = 2; k <= 8192; k <<= 1) {
        for (int jj = k >> 1; jj > 0; jj >>= 1) {
            for (int i = tid; i < 8192; i += 1024) {
                int l = i ^ jj;
                if (l > i) {
                    float ki = key[i], kl = key[l];
                    bool desc = ((i & k) == 0);
                    if (desc ? (ki < kl) : (ki > kl)) {
                        key[i] = kl; key[l] = ki;
                        int tv = val[i]; val[i] = val[l]; val[l] = tv;
                    }
                }
            }
            __syncthreads();
        }
    }

    // gather sorted boxes, count valid, init keep bits
    int lc = 0;
    for (int p2 = tid; p2 < NBOXES; p2 += 1024) {
        int o = val[p2];
        int base = (o < NCELL) ? o * 16 : (o - NCELL) * 16 + 8;
        bx[p2] = pb[base + 0]; by[p2] = pb[base + 1];
        bw[p2] = pb[base + 2]; bh[p2] = pb[base + 3];
        if (key[p2] > 0.f) lc++;
    }
    atomicAdd(cntp, lc);
    for (int wi = tid; wi < 150; wi += 1024) {
        unsigned m = 0;
        for (int b2 = 0; b2 < 32; b2++)
            if (key[wi * 32 + b2] > 0.f) m |= (1u << b2);
        keepw[wi] = m;
    }
    __syncthreads();
    const int nv = *cntp;

    for (int i = 0; i < nv; i++) {
        if (!((keepw[i >> 5] >> (i & 31)) & 1u)) continue;
        float B0 = bx[i], B1 = by[i], B2 = bw[i], B3 = bh[i];
        float ax1 = B0 - B2 * 0.5f, ax2 = B0 + B2 * 0.5f;
        float ay1 = B1 - B3 * 0.5f, ay2 = B1 + B3 * 0.5f;
        float a1 = (ax2 - ax1 + 1.f) * (ay2 - ay1 + 1.f);
        for (int p2 = i + 1 + tid; p2 < nv; p2 += 1024) {
            float px1 = bx[p2] - bw[p2] * 0.5f, px2 = bx[p2] + bw[p2] * 0.5f;
            float py1 = by[p2] - bh[p2] * 0.5f, py2 = by[p2] + bh[p2] * 0.5f;
            float iw = fminf(ax2, px2) - fmaxf(ax1, px1) + 1.f; iw = fmaxf(iw, 0.f);
            float ih = fminf(ay2, py2) - fmaxf(ay1, py1) + 1.f; ih = fmaxf(ih, 0.f);
            float inter = iw * ih;
            float a2 = (px2 - px1 + 1.f) * (py2 - py1 + 1.f);
            float iou = inter / (a1 + a2 - inter);
            if (iou >= 0.4f) atomicAnd(&keepw[p2 >> 5], ~(1u << (p2 & 31)));
        }
        __syncthreads();
    }

    float* ko = out + KEEP_BASE + ((size_t)img * 3 + cls) * NBOXES;
    for (int p2 = tid; p2 < NBOXES; p2 += 1024) {
        int o = val[p2];
        ko[o] = ((keepw[p2 >> 5] >> (p2 & 31)) & 1u) ? 1.f : 0.f;
    }
}

// ---------------- launch ----------------
extern "C" void kernel_launch(void* const* d_in, const int* in_sizes, int n_in,
                              void* d_out, int out_size)
{
    (void)in_sizes; (void)n_in; (void)out_size;
    const float* img = (const float*)d_in[0];
    const float* w1  = (const float*)d_in[1];
    const float* b1  = (const float*)d_in[2];
    const float* w2  = (const float*)d_in[3];
    const float* b2  = (const float*)d_in[4];
    const float* w3  = (const float*)d_in[5];
    const float* b3  = (const float*)d_in[6];
    const float* wd1 = (const float*)d_in[7];
    const float* bd1 = (const float*)d_in[8];
    const float* wd2 = (const float*)d_in[9];
    const float* bd2 = (const float*)d_in[10];
    float* out = (float*)d_out;

    float *p_c1, *p_p1, *p_c2, *p_p2, *p_c3, *p_part, *p_d1;
    cudaGetSymbolAddress((void**)&p_c1, g_c1);
    cudaGetSymbolAddress((void**)&p_p1, g_p1);
    cudaGetSymbolAddress((void**)&p_c2, g_c2);
    cudaGetSymbolAddress((void**)&p_p2, g_p2);
    cudaGetSymbolAddress((void**)&p_c3, g_c3);
    cudaGetSymbolAddress((void**)&p_part, g_part);
    cudaGetSymbolAddress((void**)&p_d1, g_d1);

    // dynamic smem sizes (float4 counts * 16B)
    const int SM1 = (6*6*1*32 + 9*21*1) * 16;     // 21456
    const int SM2 = (3*3*8*64 + 6*18*8) * 16;     // 87552
    const int SM3 = (3*3*16*64 + 6*18*16) * 16;   // 175104
    cudaFuncSetAttribute(conv_relu_k<3,3,32,8,64,16,4>,
                         cudaFuncAttributeMaxDynamicSharedMemorySize, SM2);
    cudaFuncSetAttribute(conv_relu_k<3,3,64,16,64,16,4>,
                         cudaFuncAttributeMaxDynamicSharedMemorySize, SM3);
    cudaFuncSetAttribute(nms_k, cudaFuncAttributeMaxDynamicSharedMemorySize, NMS_SMEM);

    // conv1: (8,160,240,3) -> (8,155,235,32)
    conv_relu_k<6,6,3,1,32,16,4><<<dim3(15,39,8), 128, SM1>>>(
        img, w1, b1, p_c1, 160, 240, 155, 235, 32, 1);
    // pool1 -> (8,77,117,32)
    {
        int total = 8*77*117*32;
        pool_k<<<(total + 255)/256, 256>>>(p_c1, p_p1, 155, 235, 77, 117, 32, total);
    }
    // conv2 -> (8,75,115,64)
    conv_relu_k<3,3,32,8,64,16,4><<<dim3(8,19,8), 256, SM2>>>(
        p_p1, w2, b2, p_c2, 77, 117, 75, 115, 64, 1);
    // pool2 -> (8,37,57,64)
    {
        int total = 8*37*57*64;
        pool_k<<<(total + 255)/256, 256>>>(p_c2, p_p2, 75, 115, 37, 57, 64, total);
    }
    // conv3 -> (8,35,55,128), two co-halves per image
    conv_relu_k<3,3,64,16,64,16,4><<<dim3(4,9,16), 256, SM3>>>(
        p_p2, w3, b3, p_c3, 37, 57, 35, 55, 128, 2);
    // dense1 split-K + reduce(+bias+relu)
    d1_partial_k<<<NSPLIT, 64>>>(p_c3, wd1, p_part);
    d1_reduce_k<<<8, 256>>>(p_part, bd1, p_d1);
    // dense2 + transform -> pred
    d2_transform_k<<<150, 256>>>(p_d1, wd2, bd2, out);
    // NMS -> keep
    nms_k<<<dim3(3, 8), 1024, NMS_SMEM>>>(out, out);
}

// round 13
// speedup vs baseline: 1.5497x; 1.5497x over previous
#include <cuda_runtime.h>
#include <math.h>

// ---------------- problem dims ----------------
// img (8,160,240,3) -> conv1 6x6x3x32 -> (8,155,235,32) -> pool -> (8,77,117,32)
// conv2 3x3x32x64 -> (8,75,115,64) -> pool -> (8,37,57,64)
// conv3 3x3x64x128 -> (8,35,55,128) -> flatten 246400
// dense1 246400x256 relu -> dense2 256x38400 -> transform -> pred (8,2400,16)
// NMS per (img, class in 0..2) over 4800 boxes -> keep (8,3,4800)

#define B_IMG 8
#define F_IN 246400
#define NCELL 2400
#define NBOXES 4800
#define PRED_ELEMS (B_IMG * NCELL * 16)       // 307200
#define KEEP_BASE PRED_ELEMS
#define NSPLIT 1925
#define KC 128

// ---------------- scratch (device globals; no allocations) ----------------
__device__ __align__(256) float g_c1[9324800];   // (8,155,235,32)
__device__ __align__(256) float g_p1[2306304];   // (8,77,117,32)
__device__ __align__(256) float g_c2[4416000];   // (8,75,115,64)
__device__ __align__(256) float g_p2[1079808];   // (8,37,57,64)
__device__ __align__(256) float g_c3[1971200];   // (8,35,55,128) = dense1 input
__device__ __align__(256) float g_part[3942400]; // (1925,8,256) dense1 split-K partials
__device__ __align__(256) float g_d1[2048];      // (8,256) dense1 output (post-relu)

__device__ __forceinline__ float sigf(float x) { return 1.f / (1.f + expf(-x)); }

// ---- packed fp32x2 helpers (sm_10x FFMA2 path) ----
#define FMA2(acc, a, b) asm("fma.rn.f32x2 %0, %1, %2, %3;" \
    : "=l"(acc) : "l"(a), "l"(b), "l"(acc))
#define PK2(d, s) asm("mov.b64 %0, {%1, %1};" : "=l"(d) : "r"(s))
#define UNPK2(lo, hi, v) asm("mov.b64 {%0, %1}, %2;" : "=f"(lo), "=f"(hi) : "l"(v))

__device__ __forceinline__ float f4c(const float4& v, int c) {
    return c == 0 ? v.x : c == 1 ? v.y : c == 2 ? v.z : v.w;
}

// ---------------- direct conv + relu, f32x2 packed, 8co x TY rows / thread ----
// smem weights: natural layout [kk][ci][co/4] float4 (co contiguous -> zero-cost pairs)
// smem patch:   [ci4][py][px] float4 (px contiguous -> conflict-free)
template<int KH, int KW, int CI, int CIP4, int COB, int TX, int TY>
__global__ void conv_relu_k(const float* __restrict__ in, const float* __restrict__ w,
                            const float* __restrict__ bias, float* __restrict__ out,
                            int IH, int IW, int OH, int OW, int CO, int coH)
{
    constexpr int NCO4 = COB / 4;
    constexpr int NCO8 = COB / 8;
    constexpr int PR = TY + KH - 1, PC = TX + KW - 1;
    constexpr int NW4 = KH * KW * CI * NCO4;   // float4 elements
    constexpr int NP4 = CIP4 * PR * PC;
    constexpr int NTHR = NCO8 * TX;

    extern __shared__ float4 sm4[];
    float4* ws = sm4;
    float4* ps = sm4 + NW4;

    const int tid = threadIdx.x;
    const int xo  = tid % TX;
    const int cg  = tid / TX;          // co-group of 8
    const int z   = blockIdx.z;
    const int img = z / coH;
    const int co0 = (z % coH) * COB;
    const int y0  = blockIdx.y * TY;
    const int x0  = blockIdx.x * TX;

    // weights -> smem, natural layout (coalesced both sides)
    for (int idx = tid; idx < NW4; idx += NTHR) {
        int cg2 = idx % NCO4;
        int r   = idx / NCO4;          // = kk*CI + ci
        ws[idx] = *(const float4*)(w + (size_t)r * CO + co0 + cg2 * 4);
    }
    // patch -> smem [ci4][py][px]
    for (int idx = tid; idx < NP4; idx += NTHR) {
        int px  = idx % PC;
        int r   = idx / PC;
        int py  = r % PR;
        int ci4 = r / PR;
        int iy = y0 + py, ix = x0 + px;
        float4 v = make_float4(0.f, 0.f, 0.f, 0.f);
        if (iy < IH && ix < IW) {
            const float* p = in + ((size_t)(img * IH + iy) * IW + ix) * CI + ci4 * 4;
            if (CI & 3) { v.x = p[0]; v.y = p[1]; v.z = p[2]; }
            else        { v = *(const float4*)p; }
        }
        ps[idx] = v;
    }
    __syncthreads();

    unsigned long long acc[TY][4];
#pragma unroll
    for (int yy = 0; yy < TY; yy++)
#pragma unroll
        for (int q = 0; q < 4; q++) acc[yy][q] = 0ULL;

    const ulonglong2* ws2 = (const ulonglong2*)ws;

#pragma unroll 1
    for (int kk = 0; kk < KH * KW; kk++) {
        const int ky = kk / KW, kx = kk % KW;
#pragma unroll 4
        for (int ci4 = 0; ci4 < CIP4; ci4++) {
            float4 pv[TY];
#pragma unroll
            for (int yy = 0; yy < TY; yy++)
                pv[yy] = ps[(ci4 * PR + yy + ky) * PC + xo + kx];
#pragma unroll
            for (int cc = 0; cc < 4; cc++) {
                if (ci4 * 4 + cc < CI) {
                    const int ci = ci4 * 4 + cc;
                    ulonglong2 wa = ws2[(kk * CI + ci) * NCO4 + cg * 2 + 0]; // co0..3
                    ulonglong2 wb = ws2[(kk * CI + ci) * NCO4 + cg * 2 + 1]; // co4..7
#pragma unroll
                    for (int yy = 0; yy < TY; yy++) {
                        unsigned long long p2;
                        PK2(p2, __float_as_uint(f4c(pv[yy], cc)));
                        FMA2(acc[yy][0], p2, wa.x);
                        FMA2(acc[yy][1], p2, wa.y);
                        FMA2(acc[yy][2], p2, wb.x);
                        FMA2(acc[yy][3], p2, wb.y);
                    }
                }
            }
        }
    }

    const int x = x0 + xo;
    if (x < OW) {
        const int co = co0 + cg * 8;
        float4 bv0 = *(const float4*)(bias + co);
        float4 bv1 = *(const float4*)(bias + co + 4);
#pragma unroll
        for (int yy = 0; yy < TY; yy++) {
            int y = y0 + yy;
            if (y < OH) {
                float4 r0, r1;
                UNPK2(r0.x, r0.y, acc[yy][0]);
                UNPK2(r0.z, r0.w, acc[yy][1]);
                UNPK2(r1.x, r1.y, acc[yy][2]);
                UNPK2(r1.z, r1.w, acc[yy][3]);
                r0.x = fmaxf(r0.x + bv0.x, 0.f); r0.y = fmaxf(r0.y + bv0.y, 0.f);
                r0.z = fmaxf(r0.z + bv0.z, 0.f); r0.w = fmaxf(r0.w + bv0.w, 0.f);
                r1.x = fmaxf(r1.x + bv1.x, 0.f); r1.y = fmaxf(r1.y + bv1.y, 0.f);
                r1.z = fmaxf(r1.z + bv1.z, 0.f); r1.w = fmaxf(r1.w + bv1.w, 0.f);
                float* op = out + ((size_t)(img * OH + y) * OW + x) * CO + co;
                *(float4*)op = r0;
                *(float4*)(op + 4) = r1;
            }
        }
    }
}

// ---------------- 2x2 max pool, stride 2, VALID, float4 over channels ----------------
__global__ void pool_k(const float* __restrict__ in, float* __restrict__ out,
                       int IH, int IW, int OH, int OW, int C4, int total4)
{
    int idx = blockIdx.x * blockDim.x + threadIdx.x;
    if (idx >= total4) return;
    int c4 = idx % C4; int t = idx / C4;
    int x = t % OW;  t /= OW;
    int y = t % OH;  int img = t / OH;
    const float4* p = (const float4*)in + ((size_t)(img * IH + 2 * y) * IW + 2 * x) * C4 + c4;
    float4 a = p[0], b = p[C4];
    float4 c = p[(size_t)IW * C4], d = p[(size_t)IW * C4 + C4];
    float4 r;
    r.x = fmaxf(fmaxf(a.x, b.x), fmaxf(c.x, d.x));
    r.y = fmaxf(fmaxf(a.y, b.y), fmaxf(c.y, d.y));
    r.z = fmaxf(fmaxf(a.z, b.z), fmaxf(c.z, d.z));
    r.w = fmaxf(fmaxf(a.w, b.w), fmaxf(c.w, d.w));
    ((float4*)out)[idx] = r;
}

// ---------------- dense1 split-K ----------------
__global__ void d1_partial_k(const float* __restrict__ x, const float* __restrict__ wd1,
                             float* __restrict__ part)
{
    __shared__ float xs[B_IMG][KC];
    const int s = blockIdx.x;
    const int k0 = s * KC;
    const int tid = threadIdx.x; // 64
    for (int i = tid; i < B_IMG * KC; i += 64) {
        int b = i >> 7, kk = i & 127;
        xs[b][kk] = x[(size_t)b * F_IN + k0 + kk];
    }
    __syncthreads();
    float4 acc[B_IMG];
#pragma unroll
    for (int b = 0; b < B_IMG; b++) acc[b] = make_float4(0.f, 0.f, 0.f, 0.f);
    const float* wp = wd1 + (size_t)k0 * 256 + tid * 4;
#pragma unroll 8
    for (int kk = 0; kk < KC; kk++) {
        float4 w = *(const float4*)wp; wp += 256;
#pragma unroll
        for (int b = 0; b < B_IMG; b++) {
            float xv = xs[b][kk];
            acc[b].x += xv * w.x; acc[b].y += xv * w.y;
            acc[b].z += xv * w.z; acc[b].w += xv * w.w;
        }
    }
#pragma unroll
    for (int b = 0; b < B_IMG; b++)
        *(float4*)(part + ((size_t)s * B_IMG + b) * 256 + tid * 4) = acc[b];
}

__global__ void d1_reduce_k(const float* __restrict__ part, const float* __restrict__ bd1,
                            float* __restrict__ d1o)
{
    int b = blockIdx.x, j = threadIdx.x;
    float s = 0.f;
    for (int si = 0; si < NSPLIT; si++)
        s += part[((size_t)si * B_IMG + b) * 256 + j];
    d1o[b * 256 + j] = fmaxf(s + bd1[j], 0.f);
}

// ---------------- dense2 + predict transform ----------------
__global__ void d2_transform_k(const float* __restrict__ d1, const float* __restrict__ wd2,
                               const float* __restrict__ bd2, float* __restrict__ pred)
{
    __shared__ float xs[B_IMG][256];
    const int tid = threadIdx.x; // 256
    for (int i = tid; i < B_IMG * 256; i += 256) xs[i >> 8][i & 255] = d1[i];
    __syncthreads();
    const int j = blockIdx.x * 256 + tid; // < 38400
    float acc[B_IMG];
#pragma unroll
    for (int b = 0; b < B_IMG; b++) acc[b] = 0.f;
    const float* wp = wd2 + j;
#pragma unroll 4
    for (int k = 0; k < 256; k++) {
        float wv = wp[(size_t)k * 38400];
#pragma unroll
        for (int b = 0; b < B_IMG; b++) acc[b] += xs[b][k] * wv;
    }
    const float bb = bd2[j];
    const int c = j & 15, cell = j >> 4;
    float off = 0.f;
    if (c == 0 || c == 8) off = (float)(cell % 60);
    else if (c == 1 || c == 9) off = (float)(cell / 60);
#pragma unroll
    for (int b = 0; b < B_IMG; b++) {
        float p = acc[b] + bb;
        float v;
        if (c < 2)        v = (sigf(p) + off) * 4.f;
        else if (c == 2)  v = expf(p) * 240.f;   // 60*4
        else if (c == 3)  v = expf(p) * 120.f;   // 30*4
        else if (c < 8)   v = sigf(p);
        else if (c < 10)  v = (p + off) * 4.f;
        else if (c == 10) v = expf(p) * 80.f;    // 20*4
        else if (c == 11) v = expf(p) * 160.f;   // 40*4
        else if (c == 12) v = p;
        else              v = sigf(p);
        pred[((size_t)b * NCELL + cell) * 16 + c] = v;
    }
}

// ---------------- per (img,class) greedy NMS ----------------
#define NMS_SMEM (8192*4 + 8192*4 + 4800*4*4 + 150*4 + 4)
__global__ void nms_k(const float* __restrict__ pred, float* __restrict__ out)
{
    const int cls = blockIdx.x;
    const int img = blockIdx.y;
    extern __shared__ char smraw[];
    float*    key   = (float*)smraw;
    int*      val   = (int*)(key + 8192);
    float*    bx    = (float*)(val + 8192);
    float*    by    = bx + NBOXES;
    float*    bw    = by + NBOXES;
    float*    bh    = bw + NBOXES;
    unsigned* keepw = (unsigned*)(bh + NBOXES);
    int*      cntp  = (int*)(keepw + 150);
    const int tid = threadIdx.x; // 1024
    const float* pb = pred + (size_t)img * (NCELL * 16);

    if (tid == 0) *cntp = 0;
    for (int i = tid; i < 8192; i += 1024) {
        float sc = -2.f;
        if (i < NBOXES) {
            int base = (i < NCELL) ? i * 16 : (i - NCELL) * 16 + 8;
            float conf = pb[base + 4];
            float c5 = pb[base + 5], c6 = pb[base + 6], c7 = pb[base + 7];
            int ci = 0; float bst = c5;
            if (c6 > bst) { bst = c6; ci = 1; }
            if (c7 > bst) { ci = 2; }
            sc = (conf > 0.5f && ci == cls) ? conf : -1.f;
        }
        key[i] = sc; val[i] = i;
    }
    __syncthreads();

    for (int k = 2; k <= 8192; k <<= 1) {
        for (int jj = k >> 1; jj > 0; jj >>= 1) {
            for (int i = tid; i < 8192; i += 1024) {
                int l = i ^ jj;
                if (l > i) {
                    float ki = key[i], kl = key[l];
                    bool desc = ((i & k) == 0);
                    if (desc ? (ki < kl) : (ki > kl)) {
                        key[i] = kl; key[l] = ki;
                        int tv = val[i]; val[i] = val[l]; val[l] = tv;
                    }
                }
            }
            __syncthreads();
        }
    }

    int lc = 0;
    for (int p2 = tid; p2 < NBOXES; p2 += 1024) {
        int o = val[p2];
        int base = (o < NCELL) ? o * 16 : (o - NCELL) * 16 + 8;
        bx[p2] = pb[base + 0]; by[p2] = pb[base + 1];
        bw[p2] = pb[base + 2]; bh[p2] = pb[base + 3];
        if (key[p2] > 0.f) lc++;
    }
    atomicAdd(cntp, lc);
    for (int wi = tid; wi < 150; wi += 1024) {
        unsigned m = 0;
        for (int b2 = 0; b2 < 32; b2++)
            if (key[wi * 32 + b2] > 0.f) m |= (1u << b2);
        keepw[wi] = m;
    }
    __syncthreads();
    const int nv = *cntp;

    for (int i = 0; i < nv; i++) {
        if (!((keepw[i >> 5] >> (i & 31)) & 1u)) continue;
        float B0 = bx[i], B1 = by[i], B2 = bw[i], B3 = bh[i];
        float ax1 = B0 - B2 * 0.5f, ax2 = B0 + B2 * 0.5f;
        float ay1 = B1 - B3 * 0.5f, ay2 = B1 + B3 * 0.5f;
        float a1 = (ax2 - ax1 + 1.f) * (ay2 - ay1 + 1.f);
        for (int p2 = i + 1 + tid; p2 < nv; p2 += 1024) {
            float px1 = bx[p2] - bw[p2] * 0.5f, px2 = bx[p2] + bw[p2] * 0.5f;
            float py1 = by[p2] - bh[p2] * 0.5f, py2 = by[p2] + bh[p2] * 0.5f;
            float iw = fminf(ax2, px2) - fmaxf(ax1, px1) + 1.f; iw = fmaxf(iw, 0.f);
            float ih = fminf(ay2, py2) - fmaxf(ay1, py1) + 1.f; ih = fmaxf(ih, 0.f);
            float inter = iw * ih;
            float a2 = (px2 - px1 + 1.f) * (py2 - py1 + 1.f);
            float iou = inter / (a1 + a2 - inter);
            if (iou >= 0.4f) atomicAnd(&keepw[p2 >> 5], ~(1u << (p2 & 31)));
        }
        __syncthreads();
    }

    float* ko = out + KEEP_BASE + ((size_t)img * 3 + cls) * NBOXES;
    for (int p2 = tid; p2 < NBOXES; p2 += 1024) {
        int o = val[p2];
        ko[o] = ((keepw[p2 >> 5] >> (p2 & 31)) & 1u) ? 1.f : 0.f;
    }
}

// ---------------- launch ----------------
extern "C" void kernel_launch(void* const* d_in, const int* in_sizes, int n_in,
                              void* d_out, int out_size)
{
    (void)in_sizes; (void)n_in; (void)out_size;
    const float* img = (const float*)d_in[0];
    const float* w1  = (const float*)d_in[1];
    const float* b1  = (const float*)d_in[2];
    const float* w2  = (const float*)d_in[3];
    const float* b2  = (const float*)d_in[4];
    const float* w3  = (const float*)d_in[5];
    const float* b3  = (const float*)d_in[6];
    const float* wd1 = (const float*)d_in[7];
    const float* bd1 = (const float*)d_in[8];
    const float* wd2 = (const float*)d_in[9];
    const float* bd2 = (const float*)d_in[10];
    float* out = (float*)d_out;

    float *p_c1, *p_p1, *p_c2, *p_p2, *p_c3, *p_part, *p_d1;
    cudaGetSymbolAddress((void**)&p_c1, g_c1);
    cudaGetSymbolAddress((void**)&p_p1, g_p1);
    cudaGetSymbolAddress((void**)&p_c2, g_c2);
    cudaGetSymbolAddress((void**)&p_p2, g_p2);
    cudaGetSymbolAddress((void**)&p_c3, g_c3);
    cudaGetSymbolAddress((void**)&p_part, g_part);
    cudaGetSymbolAddress((void**)&p_d1, g_d1);

    // dynamic smem: (NW4 + NP4) float4s * 16B
    const int SM1 = (6*6*3*8  + 1*13*37) * 16;    // 13824+7696  = 21520
    const int SM2 = (9*32*16  + 8*10*18) * 16;    // 73728+23040 = 96768
    const int SM3 = (9*64*16  + 16*10*18) * 16;   // 147456+46080= 193536
    cudaFuncSetAttribute(conv_relu_k<3,3,32,8,64,16,8>,
                         cudaFuncAttributeMaxDynamicSharedMemorySize, SM2);
    cudaFuncSetAttribute(conv_relu_k<3,3,64,16,64,16,8>,
                         cudaFuncAttributeMaxDynamicSharedMemorySize, SM3);
    cudaFuncSetAttribute(nms_k, cudaFuncAttributeMaxDynamicSharedMemorySize, NMS_SMEM);

    // conv1: (8,160,240,3) -> (8,155,235,32)   COB=32, TX=32, TY=8 -> 128 thr
    conv_relu_k<6,6,3,1,32,32,8><<<dim3(8,20,8), 128, SM1>>>(
        img, w1, b1, p_c1, 160, 240, 155, 235, 32, 1);
    // pool1 -> (8,77,117,32)
    pool_k<<<(576576 + 255)/256, 256>>>(p_c1, p_p1, 155, 235, 77, 117, 8, 576576);
    // conv2 -> (8,75,115,64)   COB=64, TX=16, TY=8 -> 128 thr
    conv_relu_k<3,3,32,8,64,16,8><<<dim3(8,10,8), 128, SM2>>>(
        p_p1, w2, b2, p_c2, 77, 117, 75, 115, 64, 1);
    // pool2 -> (8,37,57,64)
    pool_k<<<(269952 + 255)/256, 256>>>(p_c2, p_p2, 75, 115, 37, 57, 16, 269952);
    // conv3 -> (8,35,55,128), two co-halves per image
    conv_relu_k<3,3,64,16,64,16,8><<<dim3(4,5,16), 128, SM3>>>(
        p_p2, w3, b3, p_c3, 37, 57, 35, 55, 128, 2);
    // dense1 split-K + reduce(+bias+relu)
    d1_partial_k<<<NSPLIT, 64>>>(p_c3, wd1, p_part);
    d1_reduce_k<<<8, 256>>>(p_part, bd1, p_d1);
    // dense2 + transform -> pred
    d2_transform_k<<<150, 256>>>(p_d1, wd2, bd2, out);
    // NMS -> keep
    nms_k<<<dim3(3, 8), 1024, NMS_SMEM>>>(out, out);
}